// round 5
// baseline (speedup 1.0000x reference)
#include <cuda_runtime.h>

#define NB 4
#define NUM_OP 6
#define LANG_DIM 256
#define NHIDDEN 128
#define HH 128
#define WW 128
#define HWSZ (HH * WW)        // 16384
#define NC 128
#define SEM_CH (NUM_OP + 2)   // 8

__device__ float g_gw[NB][NUM_OP];
__device__ float g_bw[NB][NUM_OP];
__device__ float g_wrsum;
__device__ float g_br;

__device__ __forceinline__ float dot4(float4 a, float4 b) {
    return a.x * b.x + a.y * b.y + a.z * b.z + a.w * b.w;
}

// ---------------------------------------------------------------------------
// Kernel 1: full coefficient chain in ONE block (1024 threads = 32 warps).
// Phase 1: warp w computes actv rows 4w..4w+3 for all 4 batches (float4 loads).
// Phase 2: warp k<6 folds gamma/beta; warp 6 does wrsum/br.
// Ends with cudaTriggerProgrammaticLaunchCompletion() so the PDL-launched
// main_kernel can consume the coefficients early.
// ---------------------------------------------------------------------------
__global__ __launch_bounds__(1024) void coef_kernel(
    const float* __restrict__ lang,
    const float* __restrict__ Ws, const float* __restrict__ bs,
    const float* __restrict__ Wg, const float* __restrict__ bg,
    const float* __restrict__ Wb, const float* __restrict__ bb,
    const float* __restrict__ Wr, const float* __restrict__ br) {
    const int tid  = threadIdx.x;
    const int warp = tid >> 5;     // 0..31
    const int lane = tid & 31;

    __shared__ float4 slang4[NB][LANG_DIM / 4];   // 64 float4 per batch
    __shared__ float4 actv4[NB][NHIDDEN / 4];     // 32 float4 per batch

    // Stage all 4 lang vectors: 256 float4 total, one per thread (tid<256).
    if (tid < NB * (LANG_DIM / 4)) {
        slang4[tid >> 6][tid & 63] = reinterpret_cast<const float4*>(lang)[tid];
    }
    __syncthreads();

    // Phase 1: warp w -> rows n0..n0+3. 2 j-iters x 4 rows = 8 LDG.128, MLP=8.
    {
        const int n0 = 4 * warp;
        const float4* Ws4 = reinterpret_cast<const float4*>(Ws);

        float p[4][NB];
#pragma unroll
        for (int r = 0; r < 4; ++r)
#pragma unroll
            for (int b = 0; b < NB; ++b) p[r][b] = 0.0f;

#pragma unroll
        for (int j = 0; j < 2; ++j) {
            const int idx = lane + 32 * j;             // 0..63
            float4 wv[4];
#pragma unroll
            for (int r = 0; r < 4; ++r)
                wv[r] = Ws4[(size_t)(n0 + r) * (LANG_DIM / 4) + idx];
#pragma unroll
            for (int b = 0; b < NB; ++b) {
                const float4 lv = slang4[b][idx];
#pragma unroll
                for (int r = 0; r < 4; ++r)
                    p[r][b] += dot4(wv[r], lv);
            }
        }
#pragma unroll
        for (int off = 16; off > 0; off >>= 1)
#pragma unroll
            for (int r = 0; r < 4; ++r)
#pragma unroll
                for (int b = 0; b < NB; ++b)
                    p[r][b] += __shfl_xor_sync(0xFFFFFFFFu, p[r][b], off);

        if (lane == 0) {
#pragma unroll
            for (int r = 0; r < 4; ++r) {
                const float bias = bs[n0 + r];
#pragma unroll
                for (int b = 0; b < NB; ++b)
                    reinterpret_cast<float*>(actv4[b])[n0 + r] = p[r][b] + bias;
            }
        }
    }
    __syncthreads();

    // Phase 2: warp k<6 -> gamma/beta fold. One float4 per lane covers NHIDDEN.
    if (warp < NUM_OP) {
        const int k = warp;
        const float4 wg = reinterpret_cast<const float4*>(Wg)[(size_t)k * (NHIDDEN / 4) + lane];
        const float4 wb = reinterpret_cast<const float4*>(Wb)[(size_t)k * (NHIDDEN / 4) + lane];
        float pg[NB], pb[NB];
#pragma unroll
        for (int b = 0; b < NB; ++b) {
            const float4 a = actv4[b][lane];
            pg[b] = dot4(a, wg);
            pb[b] = dot4(a, wb);
        }
#pragma unroll
        for (int off = 16; off > 0; off >>= 1)
#pragma unroll
            for (int b = 0; b < NB; ++b) {
                pg[b] += __shfl_xor_sync(0xFFFFFFFFu, pg[b], off);
                pb[b] += __shfl_xor_sync(0xFFFFFFFFu, pb[b], off);
            }
        if (lane == 0) {
            const float wr = Wr[k];
#pragma unroll
            for (int b = 0; b < NB; ++b) {
                g_gw[b][k] = (pg[b] + bg[k]) * wr;
                g_bw[b][k] = (pb[b] + bb[k]) * wr;
            }
        }
    } else if (warp == 6 && lane == 0) {
        float s = 0.0f;
#pragma unroll
        for (int k = 0; k < NUM_OP; ++k) s += Wr[k];
        g_wrsum = s;
        g_br = br[0];
    }

    __syncthreads();
    // All coefficient writes done -> let the dependent main_kernel proceed.
    cudaTriggerProgrammaticLaunchCompletion();
}

// ---------------------------------------------------------------------------
// Kernel 2: out[b,c,hw] = x[b,c,hw]*scale[b,hw] + shift[b,hw]
// Grid (16, 4, 16) = 1024 blocks x 256 threads, 8 blocks/SM -> one wave.
// Launched with PDL: issues its 6 sem loads BEFORE cudaGridDependencySynchronize,
// overlapping its launch + load latency with coef_kernel's execution.
// ---------------------------------------------------------------------------
#define CCHUNK 8
#define TPB 256

__global__ __launch_bounds__(TPB, 8) void main_kernel(const float* __restrict__ x,
                                                      const float* __restrict__ sem,
                                                      float* __restrict__ out) {
    const int b   = blockIdx.y;
    const int c0  = blockIdx.z * CCHUNK;
    const int hw4 = blockIdx.x * TPB + threadIdx.x;   // [0, HWSZ/4)

    // Issue all 6 semantic-map loads first (independent of coef results).
    const float4* semb =
        reinterpret_cast<const float4*>(sem + (size_t)b * SEM_CH * HWSZ + 2 * HWSZ) + hw4;
    float4 sv[NUM_OP];
#pragma unroll
    for (int k = 0; k < NUM_OP; ++k)
        sv[k] = __ldg(semb + (size_t)k * (HWSZ / 4));

    // Wait for coef_kernel's trigger, then fold coefficients.
    cudaGridDependencySynchronize();

    float4 scale = make_float4(g_wrsum, g_wrsum, g_wrsum, g_wrsum);
    float4 shift = make_float4(g_br, g_br, g_br, g_br);
#pragma unroll
    for (int k = 0; k < NUM_OP; ++k) {
        const float gw = g_gw[b][k];
        const float bw = g_bw[b][k];
        scale.x += gw * sv[k].x;  scale.y += gw * sv[k].y;
        scale.z += gw * sv[k].z;  scale.w += gw * sv[k].w;
        shift.x += bw * sv[k].x;  shift.y += bw * sv[k].y;
        shift.z += bw * sv[k].z;  shift.w += bw * sv[k].w;
    }

    const float4* xb = reinterpret_cast<const float4*>(x + (size_t)b * NC * HWSZ) + hw4;
    float4*       ob = reinterpret_cast<float4*>(out + (size_t)b * NC * HWSZ) + hw4;

#pragma unroll
    for (int c = c0; c < c0 + CCHUNK; ++c) {
        const float4 xv = __ldcs(xb + (size_t)c * (HWSZ / 4));
        float4 o;
        o.x = xv.x * scale.x + shift.x;
        o.y = xv.y * scale.y + shift.y;
        o.z = xv.z * scale.z + shift.z;
        o.w = xv.w * scale.w + shift.w;
        __stcs(ob + (size_t)c * (HWSZ / 4), o);
    }
}

// ---------------------------------------------------------------------------
extern "C" void kernel_launch(void* const* d_in, const int* in_sizes, int n_in,
                              void* d_out, int out_size) {
    const float* x    = (const float*)d_in[0];
    const float* lang = (const float*)d_in[1];
    const float* sem  = (const float*)d_in[2];
    const float* Ws   = (const float*)d_in[3];
    const float* bs   = (const float*)d_in[4];
    const float* Wg   = (const float*)d_in[5];
    const float* bg   = (const float*)d_in[6];
    const float* Wb   = (const float*)d_in[7];
    const float* bb   = (const float*)d_in[8];
    const float* Wr   = (const float*)d_in[9];
    const float* br   = (const float*)d_in[10];
    float* out = (float*)d_out;

    coef_kernel<<<1, 1024>>>(lang, Ws, bs, Wg, bg, Wb, bb, Wr, br);

    dim3 grid(HWSZ / 4 / TPB, NB, NC / CCHUNK);

    cudaLaunchConfig_t cfg = {};
    cfg.gridDim = grid;
    cfg.blockDim = dim3(TPB, 1, 1);
    cfg.dynamicSmemBytes = 0;
    cfg.stream = 0;
    cudaLaunchAttribute attrs[1];
    attrs[0].id = cudaLaunchAttributeProgrammaticStreamSerialization;
    attrs[0].val.programmaticStreamSerializationAllowed = 1;
    cfg.attrs = attrs;
    cfg.numAttrs = 1;
    cudaLaunchKernelEx(&cfg, main_kernel, x, sem, out);
}